// round 7
// baseline (speedup 1.0000x reference)
#include <cuda_runtime.h>
#include <cuda_bf16.h>
#include <stdint.h>

// GraphSAGE 4-layer, dense adj. N=8192, F: 256->128->128->64.
// h = act( h@W_self + adj @ (h@W_neigh) + b ).
// Agg: mma.sync bf16 3-term split (AhBh+AhBl+AlBh, fp32 acc), BK=64,
// cp.async 3-stage B ring, compute-first overlap. R7: 512 threads (16 warps)
// for latency hiding; fused self/neigh projection kernel (BM=32, 2 CTA/SM).

static constexpr int MROWS = 8192;

__device__ float g_y [8192 * 128];
__device__ float g_h1[8192 * 128];
__device__ float g_h2[8192 * 128];
__device__ __nv_bfloat16 g_zh[8192 * 128];
__device__ __nv_bfloat16 g_zl[8192 * 128];

__device__ __forceinline__ uint32_t smem_u32(const void* p) {
    uint32_t a;
    asm("{ .reg .u64 t; cvta.to.shared.u64 t, %1; cvt.u32.u64 %0, t; }"
        : "=r"(a) : "l"(p));
    return a;
}
__device__ __forceinline__ uint32_t pack_hi2(float a, float b, float& ra, float& rb) {
    __nv_bfloat16 ha = __float2bfloat16(a), hb = __float2bfloat16(b);
    ra = a - __bfloat162float(ha);
    rb = b - __bfloat162float(hb);
    __nv_bfloat162 t(ha, hb);
    return *reinterpret_cast<uint32_t*>(&t);
}
__device__ __forceinline__ uint32_t pack2(float a, float b) {
    __nv_bfloat162 t(__float2bfloat16(a), __float2bfloat16(b));
    return *reinterpret_cast<uint32_t*>(&t);
}
__device__ __forceinline__ void ldsm_x4(uint32_t* r, uint32_t addr) {
    asm volatile("ldmatrix.sync.aligned.m8n8.x4.shared.b16 {%0,%1,%2,%3}, [%4];"
                 : "=r"(r[0]), "=r"(r[1]), "=r"(r[2]), "=r"(r[3]) : "r"(addr));
}
__device__ __forceinline__ void ldsm_x4_t(uint32_t* r, uint32_t addr) {
    asm volatile("ldmatrix.sync.aligned.m8n8.x4.trans.shared.b16 {%0,%1,%2,%3}, [%4];"
                 : "=r"(r[0]), "=r"(r[1]), "=r"(r[2]), "=r"(r[3]) : "r"(addr));
}
__device__ __forceinline__ void mma_bf16(float* d, const uint32_t* a,
                                         uint32_t b0, uint32_t b1) {
    asm volatile(
        "mma.sync.aligned.m16n8k16.row.col.f32.bf16.bf16.f32 "
        "{%0,%1,%2,%3}, {%4,%5,%6,%7}, {%8,%9}, {%0,%1,%2,%3};"
        : "+f"(d[0]), "+f"(d[1]), "+f"(d[2]), "+f"(d[3])
        : "r"(a[0]), "r"(a[1]), "r"(a[2]), "r"(a[3]), "r"(b0), "r"(b1));
}
__device__ __forceinline__ void cp16(uint32_t dst, const void* src) {
    asm volatile("cp.async.ca.shared.global [%0], [%1], 16;" :: "r"(dst), "l"(src));
}
#define CP_COMMIT() asm volatile("cp.async.commit_group;" ::: "memory")
#define CP_WAIT1()  asm volatile("cp.async.wait_group 1;" ::: "memory")

// ── aggregation: out = act(adj @ z + y); 512 threads, 16 warps (4x4) ──
template <int BN>
__global__ __launch_bounds__(512) void agg_k(
    const float* __restrict__ adj,
    const __nv_bfloat16* __restrict__ zh,
    const __nv_bfloat16* __restrict__ zl,
    const float* __restrict__ y,
    float* __restrict__ out,
    int relu)
{
    constexpr int NT = 512;
    constexpr int BM = 64, BK = 64, NCH = MROWS / BK;
    constexpr int LDA = 144;                            // 64 bf16 + 16B pad
    constexpr int ATILE = BM * LDA, ASTG = 2 * ATILE;
    constexpr int LDB = BN * 2 + 16;
    constexpr int BTILE = BK * LDB, BSTG = 2 * BTILE;
    constexpr int BOFF = 2 * ASTG;
    constexpr int CW = BN / 4;                          // warp col span
    constexpr int NTN = CW / 8;                         // 4 / 2
    constexpr int NBL = NTN / 2;                        // 2 / 1
    constexpr int BCP = (BK * BN * 2 / 16) / NT;        // 2 / 1
    constexpr int CPR = BN / 8;

    extern __shared__ __align__(128) char sm[];
    const uint32_t smb = smem_u32(sm);
    const int tid = threadIdx.x, m0 = blockIdx.x * BM;
    const int w = tid >> 5, lane = tid & 31;
    const int wr = w >> 2, wc = w & 3;                  // 4 row x 4 col warps

    float acc[NTN][4];
#pragma unroll
    for (int nt = 0; nt < NTN; nt++)
#pragma unroll
        for (int q = 0; q < 4; q++) acc[nt][q] = 0.f;

    float4 ra[2];

    auto prefA = [&](int chunk) {
        const size_t kb = (size_t)chunk * BK;
#pragma unroll
        for (int u = 0; u < 2; u++) {
            int id = tid + u * NT, row = id >> 4, c = id & 15;
            ra[u] = *reinterpret_cast<const float4*>(
                adj + (size_t)(m0 + row) * MROWS + kb + c * 4);
        }
    };
    auto cvtSTS = [&](int sa) {
#pragma unroll
        for (int u = 0; u < 2; u++) {
            int id = tid + u * NT, row = id >> 4, c = id & 15;
            float r0, r1, r2, r3;
            uint32_t h01 = pack_hi2(ra[u].x, ra[u].y, r0, r1);
            uint32_t h23 = pack_hi2(ra[u].z, ra[u].w, r2, r3);
            uint32_t off = (uint32_t)(row * LDA + c * 8);
            *reinterpret_cast<uint2*>(sm + sa * ASTG + off) = make_uint2(h01, h23);
            *reinterpret_cast<uint2*>(sm + sa * ASTG + ATILE + off) =
                make_uint2(pack2(r0, r1), pack2(r2, r3));
        }
    };
    auto issueB = [&](int chunk) {
        const uint32_t base = smb + BOFF + (chunk % 3) * BSTG;
        const size_t kb = (size_t)chunk * BK;
#pragma unroll
        for (int u = 0; u < BCP; u++) {
            int id = tid + u * NT, krow = id / CPR, c = id % CPR;
            uint32_t off = (uint32_t)(krow * LDB + c * 16);
            size_t ge = (kb + krow) * BN + c * 8;
            cp16(base + off, zh + ge);
            cp16(base + BTILE + off, zl + ge);
        }
    };

    const uint32_t a_lrow =
        (uint32_t)(wr * 16 + (lane & 15)) * LDA + (lane >> 4) * 16;

    auto compute = [&](int sa, int sb) {
        const uint32_t ab = smb + sa * ASTG;
        const uint32_t bb = smb + BOFF + sb * BSTG;
#pragma unroll
        for (int ks = 0; ks < 4; ks++) {
            uint32_t ah[4], al[4];
            uint32_t ao = ab + a_lrow + ks * 32;
            ldsm_x4(ah, ao);
            ldsm_x4(al, ao + ATILE);
            uint32_t bh[NBL][4], bl[NBL][4];
#pragma unroll
            for (int bt = 0; bt < NBL; bt++) {
                int krow = ks * 16 + (lane & 15);
                int ncol = wc * CW + bt * 16 + (lane >> 4) * 8;
                uint32_t bo = bb + (uint32_t)(krow * LDB + ncol * 2);
                ldsm_x4_t(bh[bt], bo);
                ldsm_x4_t(bl[bt], bo + BTILE);
            }
#pragma unroll
            for (int nt = 0; nt < NTN; nt++) {
                const int g = nt >> 1, p = (nt & 1) * 2;
                mma_bf16(acc[nt], ah, bh[g][p], bh[g][p + 1]);
                mma_bf16(acc[nt], ah, bl[g][p], bl[g][p + 1]);
                mma_bf16(acc[nt], al, bh[g][p], bh[g][p + 1]);
            }
        }
    };

    issueB(0); CP_COMMIT();
    issueB(1); CP_COMMIT();
    prefA(0);
    cvtSTS(0);
    prefA(1);

    for (int i = 0; i < NCH; i++) {
        const int sa = i & 1, sb = i % 3;
        CP_WAIT1();
        __syncthreads();
        compute(sa, sb);
        if (i + 2 < NCH) { issueB(i + 2); CP_COMMIT(); }
        if (i + 1 < NCH) {
            cvtSTS((i + 1) & 1);
            if (i + 2 < NCH) prefA(i + 2);
        }
    }

    const int g = lane >> 2, cp2 = (lane & 3) * 2;
    const int r0 = m0 + wr * 16 + g;
#pragma unroll
    for (int nt = 0; nt < NTN; nt++) {
        const int col = wc * CW + nt * 8 + cp2;
#pragma unroll
        for (int half = 0; half < 2; half++) {
            const size_t row = (size_t)(r0 + half * 8);
            float2 yv = *reinterpret_cast<const float2*>(y + row * BN + col);
            float v0 = acc[nt][2 * half + 0] + yv.x;
            float v1 = acc[nt][2 * half + 1] + yv.y;
            if (relu) { v0 = fmaxf(v0, 0.f); v1 = fmaxf(v1, 0.f); }
            *reinterpret_cast<float2*>(out + row * BN + col) = make_float2(v0, v1);
        }
    }
}

// ── fused projection: y = A@W[0:K] + b ; z = A@W[K:2K] -> bf16 hi/lo ──
// BM=32, BK=32, NT=256, TM=2, TN=BN/16. grid = 8192/32 = 256.
template <int BN>
__global__ __launch_bounds__(256, 2) void proj_k(
    const float* __restrict__ A,
    const float* __restrict__ W,
    const float* __restrict__ bias,
    float* __restrict__ yout,
    __nv_bfloat16* __restrict__ zh,
    __nv_bfloat16* __restrict__ zl,
    int K)
{
    constexpr int NT = 256, BM = 32, BK = 32, TM = 2, TN = BN / 16;
    constexpr int BF4 = (BK * BN / 4) / NT;             // 4 / 2
    __shared__ float As[BK][BM];
    __shared__ float Bs[BK][BN];
    __shared__ float Bn[BK][BN];

    const float* Ws = W;
    const float* Wn = W + (size_t)K * BN;
    const int tid = threadIdx.x;
    const int tx = tid % (BN / TN), ty = tid / (BN / TN);   // 16 x 16
    const int m0 = blockIdx.x * BM;

    float accS[TM][TN], accN[TM][TN];
#pragma unroll
    for (int i = 0; i < TM; i++)
#pragma unroll
        for (int j = 0; j < TN; j++) { accS[i][j] = 0.f; accN[i][j] = 0.f; }

    float4 ra, rs[BF4], rn[BF4];
    const int nkt = K / BK;

    {
        int row = tid >> 3, k4 = tid & 7;
        ra = *reinterpret_cast<const float4*>(A + (size_t)(m0 + row) * K + k4 * 4);
    }
#pragma unroll
    for (int u = 0; u < BF4; u++) {
        int id = tid + u * NT, row = id / (BN / 4), c4 = id % (BN / 4);
        rs[u] = *reinterpret_cast<const float4*>(Ws + (size_t)row * BN + c4 * 4);
        rn[u] = *reinterpret_cast<const float4*>(Wn + (size_t)row * BN + c4 * 4);
    }

    for (int kt = 0; kt < nkt; ++kt) {
        {
            int row = tid >> 3, k4 = tid & 7;
            As[k4 * 4 + 0][row] = ra.x; As[k4 * 4 + 1][row] = ra.y;
            As[k4 * 4 + 2][row] = ra.z; As[k4 * 4 + 3][row] = ra.w;
        }
#pragma unroll
        for (int u = 0; u < BF4; u++) {
            int id = tid + u * NT, row = id / (BN / 4), c4 = id % (BN / 4);
            *reinterpret_cast<float4*>(&Bs[row][c4 * 4]) = rs[u];
            *reinterpret_cast<float4*>(&Bn[row][c4 * 4]) = rn[u];
        }
        __syncthreads();
        if (kt + 1 < nkt) {
            const int kb = (kt + 1) * BK;
            {
                int row = tid >> 3, k4 = tid & 7;
                ra = *reinterpret_cast<const float4*>(
                    A + (size_t)(m0 + row) * K + kb + k4 * 4);
            }
#pragma unroll
            for (int u = 0; u < BF4; u++) {
                int id = tid + u * NT, row = id / (BN / 4), c4 = id % (BN / 4);
                rs[u] = *reinterpret_cast<const float4*>(
                    Ws + (size_t)(kb + row) * BN + c4 * 4);
                rn[u] = *reinterpret_cast<const float4*>(
                    Wn + (size_t)(kb + row) * BN + c4 * 4);
            }
        }
#pragma unroll
        for (int k = 0; k < BK; k++) {
            float a0 = As[k][ty * TM], a1 = As[k][ty * TM + 1];
            float bs[TN], bn[TN];
#pragma unroll
            for (int j = 0; j < TN; j += 4) {
                *reinterpret_cast<float4*>(bs + j) =
                    *reinterpret_cast<const float4*>(&Bs[k][tx * TN + j]);
                *reinterpret_cast<float4*>(bn + j) =
                    *reinterpret_cast<const float4*>(&Bn[k][tx * TN + j]);
            }
#pragma unroll
            for (int j = 0; j < TN; j++) {
                accS[0][j] = fmaf(a0, bs[j], accS[0][j]);
                accS[1][j] = fmaf(a1, bs[j], accS[1][j]);
                accN[0][j] = fmaf(a0, bn[j], accN[0][j]);
                accN[1][j] = fmaf(a1, bn[j], accN[1][j]);
            }
        }
        __syncthreads();
    }

#pragma unroll
    for (int i = 0; i < TM; i++) {
        const int row = m0 + ty * TM + i;
#pragma unroll
        for (int j = 0; j < TN; j += 4) {
            const int col = tx * TN + j;
            float4 v = make_float4(accS[i][j], accS[i][j+1], accS[i][j+2], accS[i][j+3]);
            float4 c = *reinterpret_cast<const float4*>(bias + col);
            v.x += c.x; v.y += c.y; v.z += c.z; v.w += c.w;
            *reinterpret_cast<float4*>(yout + (size_t)row * BN + col) = v;
        }
#pragma unroll
        for (int j = 0; j < TN; j += 2) {
            const int col = tx * TN + j;
            float r0, r1;
            uint32_t h = pack_hi2(accN[i][j], accN[i][j + 1], r0, r1);
            *reinterpret_cast<uint32_t*>(zh + (size_t)row * BN + col) = h;
            *reinterpret_cast<uint32_t*>(zl + (size_t)row * BN + col) = pack2(r0, r1);
        }
    }
}

extern "C" void kernel_launch(void* const* d_in, const int* in_sizes, int n_in,
                              void* d_out, int out_size)
{
    const float* x   = (const float*)d_in[0];
    const float* adj = (const float*)d_in[1];
    const float* W1  = (const float*)d_in[2];
    const float* b1  = (const float*)d_in[3];
    const float* W2  = (const float*)d_in[4];
    const float* b2  = (const float*)d_in[5];
    const float* W3  = (const float*)d_in[6];
    const float* b3  = (const float*)d_in[7];
    const float* W4  = (const float*)d_in[8];
    const float* b4  = (const float*)d_in[9];
    float* out = (float*)d_out;

    float *y, *h1, *h2;
    __nv_bfloat16 *zh, *zl;
    cudaGetSymbolAddress((void**)&y,  g_y);
    cudaGetSymbolAddress((void**)&h1, g_h1);
    cudaGetSymbolAddress((void**)&h2, g_h2);
    cudaGetSymbolAddress((void**)&zh, g_zh);
    cudaGetSymbolAddress((void**)&zl, g_zl);

    constexpr int SM128 = 2 * (2 * 64 * 144) + 3 * (2 * 64 * (128 * 2 + 16)); // 141312
    constexpr int SM64  = 2 * (2 * 64 * 144) + 3 * (2 * 64 * (64 * 2 + 16));  //  92160
    cudaFuncSetAttribute(agg_k<128>, cudaFuncAttributeMaxDynamicSharedMemorySize, SM128);
    cudaFuncSetAttribute(agg_k<64>,  cudaFuncAttributeMaxDynamicSharedMemorySize, SM64);

    const dim3 pg(MROWS / 32);
    const dim3 ag(MROWS / 64);

    proj_k<128><<<pg, 256>>>(x, W1, b1, y, zh, zl, 256);
    agg_k<128><<<ag, 512, SM128>>>(adj, zh, zl, y, h1, 1);

    proj_k<128><<<pg, 256>>>(h1, W2, b2, y, zh, zl, 128);
    agg_k<128><<<ag, 512, SM128>>>(adj, zh, zl, y, h2, 1);

    proj_k<128><<<pg, 256>>>(h2, W3, b3, y, zh, zl, 128);
    agg_k<128><<<ag, 512, SM128>>>(adj, zh, zl, y, h1, 1);

    proj_k<64><<<pg, 256>>>(h1, W4, b4, y, zh, zl, 128);
    agg_k<64><<<ag, 512, SM64>>>(adj, zh, zl, y, out, 0);
}

// round 8
// speedup vs baseline: 1.0754x; 1.0754x over previous
#include <cuda_runtime.h>
#include <cuda_bf16.h>
#include <stdint.h>

// GraphSAGE 4-layer, dense adj. N=8192, F: 256->128->128->64.
// h = act( h@W_self + adj @ (h@W_neigh) + b ).
// Agg: mma.sync bf16 3-term split (AhBh+AhBl+AlBh, fp32 acc), BK=64,
// cp.async 3-stage B ring, compute-first overlap.
// R8: split-K warp specialization — 16 warps, warps 0-7 do ks{0,1},
// warps 8-15 do ks{2,3} of each chunk (same total ldsm/MMA as the 8-warp
// version, 2x eligible warps per SMSP); partials merged via smem at the end.

static constexpr int MROWS = 8192;

__device__ float g_y [8192 * 128];
__device__ float g_h1[8192 * 128];
__device__ float g_h2[8192 * 128];
__device__ __nv_bfloat16 g_zh[8192 * 128];
__device__ __nv_bfloat16 g_zl[8192 * 128];

__device__ __forceinline__ uint32_t smem_u32(const void* p) {
    uint32_t a;
    asm("{ .reg .u64 t; cvta.to.shared.u64 t, %1; cvt.u32.u64 %0, t; }"
        : "=r"(a) : "l"(p));
    return a;
}
__device__ __forceinline__ uint32_t pack_hi2(float a, float b, float& ra, float& rb) {
    __nv_bfloat16 ha = __float2bfloat16(a), hb = __float2bfloat16(b);
    ra = a - __bfloat162float(ha);
    rb = b - __bfloat162float(hb);
    __nv_bfloat162 t(ha, hb);
    return *reinterpret_cast<uint32_t*>(&t);
}
__device__ __forceinline__ uint32_t pack2(float a, float b) {
    __nv_bfloat162 t(__float2bfloat16(a), __float2bfloat16(b));
    return *reinterpret_cast<uint32_t*>(&t);
}
__device__ __forceinline__ void ldsm_x4(uint32_t* r, uint32_t addr) {
    asm volatile("ldmatrix.sync.aligned.m8n8.x4.shared.b16 {%0,%1,%2,%3}, [%4];"
                 : "=r"(r[0]), "=r"(r[1]), "=r"(r[2]), "=r"(r[3]) : "r"(addr));
}
__device__ __forceinline__ void ldsm_x4_t(uint32_t* r, uint32_t addr) {
    asm volatile("ldmatrix.sync.aligned.m8n8.x4.trans.shared.b16 {%0,%1,%2,%3}, [%4];"
                 : "=r"(r[0]), "=r"(r[1]), "=r"(r[2]), "=r"(r[3]) : "r"(addr));
}
__device__ __forceinline__ void mma_bf16(float* d, const uint32_t* a,
                                         uint32_t b0, uint32_t b1) {
    asm volatile(
        "mma.sync.aligned.m16n8k16.row.col.f32.bf16.bf16.f32 "
        "{%0,%1,%2,%3}, {%4,%5,%6,%7}, {%8,%9}, {%0,%1,%2,%3};"
        : "+f"(d[0]), "+f"(d[1]), "+f"(d[2]), "+f"(d[3])
        : "r"(a[0]), "r"(a[1]), "r"(a[2]), "r"(a[3]), "r"(b0), "r"(b1));
}
__device__ __forceinline__ void cp16(uint32_t dst, const void* src) {
    asm volatile("cp.async.ca.shared.global [%0], [%1], 16;" :: "r"(dst), "l"(src));
}
#define CP_COMMIT() asm volatile("cp.async.commit_group;" ::: "memory")
#define CP_WAIT1()  asm volatile("cp.async.wait_group 1;" ::: "memory")

// ── aggregation: out = act(adj @ z + y); 512 threads, split-K warps ──
template <int BN>
__global__ __launch_bounds__(512) void agg_k(
    const float* __restrict__ adj,
    const __nv_bfloat16* __restrict__ zh,
    const __nv_bfloat16* __restrict__ zl,
    const float* __restrict__ y,
    float* __restrict__ out,
    int relu)
{
    constexpr int NT = 512;
    constexpr int BM = 64, BK = 64, NCH = MROWS / BK;
    constexpr int LDA = 144;
    constexpr int ATILE = BM * LDA, ASTG = 2 * ATILE;
    constexpr int LDB = BN * 2 + 16;
    constexpr int BTILE = BK * LDB, BSTG = 2 * BTILE;
    constexpr int BOFF = 2 * ASTG;
    constexpr int CW = BN / 4;                  // warp col span (32 / 16)
    constexpr int NTN = CW / 8;                 // 4 / 2
    constexpr int NBL = NTN / 2;                // 2 / 1
    constexpr int BCP = (BK * BN * 2 / 16) / NT;// 2 / 1
    constexpr int CPR = BN / 8;

    extern __shared__ __align__(128) char sm[];
    const uint32_t smb = smem_u32(sm);
    const int tid = threadIdx.x, m0 = blockIdx.x * BM;
    const int w = tid >> 5, lane = tid & 31;
    const int kw = w >> 3;                      // k-half (0/1)
    const int wi = w & 7;
    const int wr = wi >> 2, wc = wi & 3;        // 2 row x 4 col tiles of 32x32

    float acc[2][NTN][4];
#pragma unroll
    for (int mt = 0; mt < 2; mt++)
#pragma unroll
        for (int nt = 0; nt < NTN; nt++)
#pragma unroll
            for (int q = 0; q < 4; q++) acc[mt][nt][q] = 0.f;

    float4 ra[2];

    auto prefA = [&](int chunk) {
        const size_t kb = (size_t)chunk * BK;
#pragma unroll
        for (int u = 0; u < 2; u++) {
            int id = tid + u * NT, row = id >> 4, c = id & 15;
            ra[u] = *reinterpret_cast<const float4*>(
                adj + (size_t)(m0 + row) * MROWS + kb + c * 4);
        }
    };
    auto cvtSTS = [&](int sa) {
#pragma unroll
        for (int u = 0; u < 2; u++) {
            int id = tid + u * NT, row = id >> 4, c = id & 15;
            float r0, r1, r2, r3;
            uint32_t h01 = pack_hi2(ra[u].x, ra[u].y, r0, r1);
            uint32_t h23 = pack_hi2(ra[u].z, ra[u].w, r2, r3);
            uint32_t off = (uint32_t)(row * LDA + c * 8);
            *reinterpret_cast<uint2*>(sm + sa * ASTG + off) = make_uint2(h01, h23);
            *reinterpret_cast<uint2*>(sm + sa * ASTG + ATILE + off) =
                make_uint2(pack2(r0, r1), pack2(r2, r3));
        }
    };
    auto issueB = [&](int chunk) {
        const uint32_t base = smb + BOFF + (chunk % 3) * BSTG;
        const size_t kb = (size_t)chunk * BK;
#pragma unroll
        for (int u = 0; u < BCP; u++) {
            int id = tid + u * NT, krow = id / CPR, c = id % CPR;
            uint32_t off = (uint32_t)(krow * LDB + c * 16);
            size_t ge = (kb + krow) * BN + c * 8;
            cp16(base + off, zh + ge);
            cp16(base + BTILE + off, zl + ge);
        }
    };

    const uint32_t a_lrow =
        (uint32_t)(wr * 32 + (lane & 15)) * LDA + (lane >> 4) * 16;

    auto compute = [&](int sa, int sb) {
        const uint32_t ab = smb + sa * ASTG;
        const uint32_t bb = smb + BOFF + sb * BSTG;
#pragma unroll
        for (int s = 0; s < 2; s++) {
            const int ks = kw * 2 + s;
            uint32_t ah[2][4], al[2][4];
#pragma unroll
            for (int mt = 0; mt < 2; mt++) {
                uint32_t ao = ab + a_lrow + mt * (16 * LDA) + ks * 32;
                ldsm_x4(ah[mt], ao);
                ldsm_x4(al[mt], ao + ATILE);
            }
            uint32_t bh[NBL][4], bl[NBL][4];
#pragma unroll
            for (int bt = 0; bt < NBL; bt++) {
                int krow = ks * 16 + (lane & 15);
                int ncol = wc * CW + bt * 16 + (lane >> 4) * 8;
                uint32_t bo = bb + (uint32_t)(krow * LDB + ncol * 2);
                ldsm_x4_t(bh[bt], bo);
                ldsm_x4_t(bl[bt], bo + BTILE);
            }
#pragma unroll
            for (int mt = 0; mt < 2; mt++)
#pragma unroll
                for (int nt = 0; nt < NTN; nt++) {
                    const int g = nt >> 1, p = (nt & 1) * 2;
                    mma_bf16(acc[mt][nt], ah[mt], bh[g][p], bh[g][p + 1]);
                    mma_bf16(acc[mt][nt], ah[mt], bl[g][p], bl[g][p + 1]);
                    mma_bf16(acc[mt][nt], al[mt], bh[g][p], bh[g][p + 1]);
                }
        }
    };

    issueB(0); CP_COMMIT();
    issueB(1); CP_COMMIT();
    prefA(0);
    cvtSTS(0);
    prefA(1);

    for (int i = 0; i < NCH; i++) {
        const int sa = i & 1, sb = i % 3;
        CP_WAIT1();
        __syncthreads();
        compute(sa, sb);
        if (i + 2 < NCH) { issueB(i + 2); CP_COMMIT(); }
        if (i + 1 < NCH) {
            cvtSTS((i + 1) & 1);
            if (i + 2 < NCH) prefA(i + 2);
        }
    }

    // merge k-halves: warps 8-15 publish partials, warps 0-7 add + store.
    __syncthreads();
    float* ps = reinterpret_cast<float*>(sm);
    if (kw == 1) {
#pragma unroll
        for (int mt = 0; mt < 2; mt++)
#pragma unroll
            for (int nt = 0; nt < NTN; nt++)
#pragma unroll
                for (int q = 0; q < 4; q++)
                    ps[((((wi * 2 + mt) * NTN + nt) * 4) + q) * 32 + lane] =
                        acc[mt][nt][q];
    }
    __syncthreads();
    if (kw == 0) {
        const int g = lane >> 2, cp2 = (lane & 3) * 2;
#pragma unroll
        for (int mt = 0; mt < 2; mt++) {
            const int r0 = m0 + wr * 32 + mt * 16 + g;
#pragma unroll
            for (int nt = 0; nt < NTN; nt++) {
                const int col = wc * CW + nt * 8 + cp2;
                float p[4];
#pragma unroll
                for (int q = 0; q < 4; q++)
                    p[q] = acc[mt][nt][q] +
                        ps[((((wi * 2 + mt) * NTN + nt) * 4) + q) * 32 + lane];
#pragma unroll
                for (int half = 0; half < 2; half++) {
                    const size_t row = (size_t)(r0 + half * 8);
                    float2 yv = *reinterpret_cast<const float2*>(y + row * BN + col);
                    float v0 = p[2 * half + 0] + yv.x;
                    float v1 = p[2 * half + 1] + yv.y;
                    if (relu) { v0 = fmaxf(v0, 0.f); v1 = fmaxf(v1, 0.f); }
                    *reinterpret_cast<float2*>(out + row * BN + col) =
                        make_float2(v0, v1);
                }
            }
        }
    }
}

// ── fused projection: y = A@W[0:K] + b ; z = A@W[K:2K] -> bf16 hi/lo ──
template <int BN>
__global__ __launch_bounds__(256, 2) void proj_k(
    const float* __restrict__ A,
    const float* __restrict__ W,
    const float* __restrict__ bias,
    float* __restrict__ yout,
    __nv_bfloat16* __restrict__ zh,
    __nv_bfloat16* __restrict__ zl,
    int K)
{
    constexpr int NT = 256, BM = 32, BK = 32, TM = 2, TN = BN / 16;
    constexpr int BF4 = (BK * BN / 4) / NT;
    __shared__ float As[BK][BM];
    __shared__ float Bs[BK][BN];
    __shared__ float Bn[BK][BN];

    const float* Ws = W;
    const float* Wn = W + (size_t)K * BN;
    const int tid = threadIdx.x;
    const int tx = tid % (BN / TN), ty = tid / (BN / TN);
    const int m0 = blockIdx.x * BM;

    float accS[TM][TN], accN[TM][TN];
#pragma unroll
    for (int i = 0; i < TM; i++)
#pragma unroll
        for (int j = 0; j < TN; j++) { accS[i][j] = 0.f; accN[i][j] = 0.f; }

    float4 ra, rs[BF4], rn[BF4];
    const int nkt = K / BK;

    {
        int row = tid >> 3, k4 = tid & 7;
        ra = *reinterpret_cast<const float4*>(A + (size_t)(m0 + row) * K + k4 * 4);
    }
#pragma unroll
    for (int u = 0; u < BF4; u++) {
        int id = tid + u * NT, row = id / (BN / 4), c4 = id % (BN / 4);
        rs[u] = *reinterpret_cast<const float4*>(Ws + (size_t)row * BN + c4 * 4);
        rn[u] = *reinterpret_cast<const float4*>(Wn + (size_t)row * BN + c4 * 4);
    }

    for (int kt = 0; kt < nkt; ++kt) {
        {
            int row = tid >> 3, k4 = tid & 7;
            As[k4 * 4 + 0][row] = ra.x; As[k4 * 4 + 1][row] = ra.y;
            As[k4 * 4 + 2][row] = ra.z; As[k4 * 4 + 3][row] = ra.w;
        }
#pragma unroll
        for (int u = 0; u < BF4; u++) {
            int id = tid + u * NT, row = id / (BN / 4), c4 = id % (BN / 4);
            *reinterpret_cast<float4*>(&Bs[row][c4 * 4]) = rs[u];
            *reinterpret_cast<float4*>(&Bn[row][c4 * 4]) = rn[u];
        }
        __syncthreads();
        if (kt + 1 < nkt) {
            const int kb = (kt + 1) * BK;
            {
                int row = tid >> 3, k4 = tid & 7;
                ra = *reinterpret_cast<const float4*>(
                    A + (size_t)(m0 + row) * K + kb + k4 * 4);
            }
#pragma unroll
            for (int u = 0; u < BF4; u++) {
                int id = tid + u * NT, row = id / (BN / 4), c4 = id % (BN / 4);
                rs[u] = *reinterpret_cast<const float4*>(
                    Ws + (size_t)(kb + row) * BN + c4 * 4);
                rn[u] = *reinterpret_cast<const float4*>(
                    Wn + (size_t)(kb + row) * BN + c4 * 4);
            }
        }
#pragma unroll
        for (int k = 0; k < BK; k++) {
            float a0 = As[k][ty * TM], a1 = As[k][ty * TM + 1];
            float bs[TN], bn[TN];
#pragma unroll
            for (int j = 0; j < TN; j += 4) {
                *reinterpret_cast<float4*>(bs + j) =
                    *reinterpret_cast<const float4*>(&Bs[k][tx * TN + j]);
                *reinterpret_cast<float4*>(bn + j) =
                    *reinterpret_cast<const float4*>(&Bn[k][tx * TN + j]);
            }
#pragma unroll
            for (int j = 0; j < TN; j++) {
                accS[0][j] = fmaf(a0, bs[j], accS[0][j]);
                accS[1][j] = fmaf(a1, bs[j], accS[1][j]);
                accN[0][j] = fmaf(a0, bn[j], accN[0][j]);
                accN[1][j] = fmaf(a1, bn[j], accN[1][j]);
            }
        }
        __syncthreads();
    }

#pragma unroll
    for (int i = 0; i < TM; i++) {
        const int row = m0 + ty * TM + i;
#pragma unroll
        for (int j = 0; j < TN; j += 4) {
            const int col = tx * TN + j;
            float4 v = make_float4(accS[i][j], accS[i][j+1], accS[i][j+2], accS[i][j+3]);
            float4 c = *reinterpret_cast<const float4*>(bias + col);
            v.x += c.x; v.y += c.y; v.z += c.z; v.w += c.w;
            *reinterpret_cast<float4*>(yout + (size_t)row * BN + col) = v;
        }
#pragma unroll
        for (int j = 0; j < TN; j += 2) {
            const int col = tx * TN + j;
            float r0, r1;
            uint32_t h = pack_hi2(accN[i][j], accN[i][j + 1], r0, r1);
            *reinterpret_cast<uint32_t*>(zh + (size_t)row * BN + col) = h;
            *reinterpret_cast<uint32_t*>(zl + (size_t)row * BN + col) = pack2(r0, r1);
        }
    }
}

extern "C" void kernel_launch(void* const* d_in, const int* in_sizes, int n_in,
                              void* d_out, int out_size)
{
    const float* x   = (const float*)d_in[0];
    const float* adj = (const float*)d_in[1];
    const float* W1  = (const float*)d_in[2];
    const float* b1  = (const float*)d_in[3];
    const float* W2  = (const float*)d_in[4];
    const float* b2  = (const float*)d_in[5];
    const float* W3  = (const float*)d_in[6];
    const float* b3  = (const float*)d_in[7];
    const float* W4  = (const float*)d_in[8];
    const float* b4  = (const float*)d_in[9];
    float* out = (float*)d_out;

    float *y, *h1, *h2;
    __nv_bfloat16 *zh, *zl;
    cudaGetSymbolAddress((void**)&y,  g_y);
    cudaGetSymbolAddress((void**)&h1, g_h1);
    cudaGetSymbolAddress((void**)&h2, g_h2);
    cudaGetSymbolAddress((void**)&zh, g_zh);
    cudaGetSymbolAddress((void**)&zl, g_zl);

    constexpr int SM128 = 2 * (2 * 64 * 144) + 3 * (2 * 64 * (128 * 2 + 16)); // 141312
    constexpr int SM64  = 2 * (2 * 64 * 144) + 3 * (2 * 64 * (64 * 2 + 16));  //  92160
    cudaFuncSetAttribute(agg_k<128>, cudaFuncAttributeMaxDynamicSharedMemorySize, SM128);
    cudaFuncSetAttribute(agg_k<64>,  cudaFuncAttributeMaxDynamicSharedMemorySize, SM64);

    const dim3 pg(MROWS / 32);
    const dim3 ag(MROWS / 64);

    proj_k<128><<<pg, 256>>>(x, W1, b1, y, zh, zl, 256);
    agg_k<128><<<ag, 512, SM128>>>(adj, zh, zl, y, h1, 1);

    proj_k<128><<<pg, 256>>>(h1, W2, b2, y, zh, zl, 128);
    agg_k<128><<<ag, 512, SM128>>>(adj, zh, zl, y, h2, 1);

    proj_k<128><<<pg, 256>>>(h2, W3, b3, y, zh, zl, 128);
    agg_k<128><<<ag, 512, SM128>>>(adj, zh, zl, y, h1, 1);

    proj_k<64><<<pg, 256>>>(h1, W4, b4, y, zh, zl, 128);
    agg_k<64><<<ag, 512, SM64>>>(adj, zh, zl, y, out, 0);
}

// round 9
// speedup vs baseline: 1.3471x; 1.2526x over previous
#include <cuda_runtime.h>
#include <cuda_fp16.h>
#include <stdint.h>

// GraphSAGE 4-layer, dense adj. N=8192, F: 256->128->128->64.
// h = act( h@W_self + adj @ (h@W_neigh) + b ).
// R9: fp16 2-term aggregation. adj scaled by 4096, split exactly into
// fp16 hi+lo (residual ~2^-22); z single fp16 (error ~2^-12 -> ~3e-4 final).
// adj@z = (Ah@Z + Al@Z)/4096, fp32 accum. Halves MMA count and B traffic
// vs the bf16 3-term scheme. Skeleton: 512-thread split-K warps, 2-stage A,
// 3-stage cp.async B ring, compute-first overlap, smem k-merge.

static constexpr int MROWS = 8192;
static constexpr float A_SCALE = 4096.0f;
static constexpr float A_INV   = 1.0f / 4096.0f;

__device__ float g_y [8192 * 128];
__device__ float g_h1[8192 * 128];
__device__ float g_h2[8192 * 128];
__device__ __half g_zh[8192 * 128];

__device__ __forceinline__ uint32_t smem_u32(const void* p) {
    uint32_t a;
    asm("{ .reg .u64 t; cvta.to.shared.u64 t, %1; cvt.u32.u64 %0, t; }"
        : "=r"(a) : "l"(p));
    return a;
}
__device__ __forceinline__ uint32_t packh2(float a, float b) {
    __half2 t = __floats2half2_rn(a, b);
    return *reinterpret_cast<uint32_t*>(&t);
}
__device__ __forceinline__ uint32_t packh_hi2(float a, float b, float& ra, float& rb) {
    __half ha = __float2half_rn(a), hb = __float2half_rn(b);
    ra = a - __half2float(ha);
    rb = b - __half2float(hb);
    __half2 t = __halves2half2(ha, hb);
    return *reinterpret_cast<uint32_t*>(&t);
}
__device__ __forceinline__ void ldsm_x4(uint32_t* r, uint32_t addr) {
    asm volatile("ldmatrix.sync.aligned.m8n8.x4.shared.b16 {%0,%1,%2,%3}, [%4];"
                 : "=r"(r[0]), "=r"(r[1]), "=r"(r[2]), "=r"(r[3]) : "r"(addr));
}
__device__ __forceinline__ void ldsm_x4_t(uint32_t* r, uint32_t addr) {
    asm volatile("ldmatrix.sync.aligned.m8n8.x4.trans.shared.b16 {%0,%1,%2,%3}, [%4];"
                 : "=r"(r[0]), "=r"(r[1]), "=r"(r[2]), "=r"(r[3]) : "r"(addr));
}
__device__ __forceinline__ void mma_f16(float* d, const uint32_t* a,
                                        uint32_t b0, uint32_t b1) {
    asm volatile(
        "mma.sync.aligned.m16n8k16.row.col.f32.f16.f16.f32 "
        "{%0,%1,%2,%3}, {%4,%5,%6,%7}, {%8,%9}, {%0,%1,%2,%3};"
        : "+f"(d[0]), "+f"(d[1]), "+f"(d[2]), "+f"(d[3])
        : "r"(a[0]), "r"(a[1]), "r"(a[2]), "r"(a[3]), "r"(b0), "r"(b1));
}
__device__ __forceinline__ void cp16(uint32_t dst, const void* src) {
    asm volatile("cp.async.ca.shared.global [%0], [%1], 16;" :: "r"(dst), "l"(src));
}
#define CP_COMMIT() asm volatile("cp.async.commit_group;" ::: "memory")
#define CP_WAIT1()  asm volatile("cp.async.wait_group 1;" ::: "memory")

// ── aggregation: out = act(adj @ z + y); 512 threads, split-K warps ──
template <int BN>
__global__ __launch_bounds__(512) void agg_k(
    const float* __restrict__ adj,
    const __half* __restrict__ zh,
    const float* __restrict__ y,
    float* __restrict__ out,
    int relu)
{
    constexpr int NT = 512;
    constexpr int BM = 64, BK = 64, NCH = MROWS / BK;
    constexpr int LDA = 144;                         // 64 fp16 (128B) + 16B pad
    constexpr int ATILE = BM * LDA, ASTG = 2 * ATILE;   // hi+lo per stage
    constexpr int LDB = BN * 2 + 16;
    constexpr int BTILE = BK * LDB;                  // single-precision B
    constexpr int BOFF = 2 * ASTG;
    constexpr int CW = BN / 4;                       // warp col span (32/16)
    constexpr int NTN = CW / 8;                      // 4 / 2
    constexpr int NBL = NTN / 2;                     // 2 / 1
    constexpr int NCP = BK * BN * 2 / 16;            // cp16 ops per chunk
    constexpr int BCP = (NCP + NT - 1) / NT;         // 2 / 1
    constexpr int CPR = BN / 8;                      // cp16 per B row

    extern __shared__ __align__(128) char sm[];
    const uint32_t smb = smem_u32(sm);
    const int tid = threadIdx.x, m0 = blockIdx.x * BM;
    const int w = tid >> 5, lane = tid & 31;
    const int kw = w >> 3;                           // k-half
    const int wi = w & 7;
    const int wr = wi >> 2, wc = wi & 3;             // 2 x 4 tiles of 32x32

    float acc[2][NTN][4];
#pragma unroll
    for (int mt = 0; mt < 2; mt++)
#pragma unroll
        for (int nt = 0; nt < NTN; nt++)
#pragma unroll
            for (int q = 0; q < 4; q++) acc[mt][nt][q] = 0.f;

    float4 ra[2];

    auto prefA = [&](int chunk) {
        const size_t kb = (size_t)chunk * BK;
#pragma unroll
        for (int u = 0; u < 2; u++) {
            int id = tid + u * NT, row = id >> 4, c = id & 15;
            ra[u] = *reinterpret_cast<const float4*>(
                adj + (size_t)(m0 + row) * MROWS + kb + c * 4);
        }
    };
    auto cvtSTS = [&](int sa) {
#pragma unroll
        for (int u = 0; u < 2; u++) {
            int id = tid + u * NT, row = id >> 4, c = id & 15;
            float r0, r1, r2, r3;
            uint32_t h01 = packh_hi2(ra[u].x * A_SCALE, ra[u].y * A_SCALE, r0, r1);
            uint32_t h23 = packh_hi2(ra[u].z * A_SCALE, ra[u].w * A_SCALE, r2, r3);
            uint32_t off = (uint32_t)(row * LDA + c * 8);
            *reinterpret_cast<uint2*>(sm + sa * ASTG + off) = make_uint2(h01, h23);
            *reinterpret_cast<uint2*>(sm + sa * ASTG + ATILE + off) =
                make_uint2(packh2(r0, r1), packh2(r2, r3));
        }
    };
    auto issueB = [&](int chunk) {
        const uint32_t base = smb + BOFF + (chunk % 3) * BTILE;
        const size_t kb = (size_t)chunk * BK;
#pragma unroll
        for (int u = 0; u < BCP; u++) {
            int id = tid + u * NT;
            if (NCP % NT == 0 || id < NCP) {
                int krow = id / CPR, c = id % CPR;
                uint32_t off = (uint32_t)(krow * LDB + c * 16);
                cp16(base + off, zh + (kb + krow) * BN + c * 8);
            }
        }
    };

    const uint32_t a_lrow =
        (uint32_t)(wr * 32 + (lane & 15)) * LDA + (lane >> 4) * 16;

    auto compute = [&](int sa, int sb) {
        const uint32_t ab = smb + sa * ASTG;
        const uint32_t bb = smb + BOFF + sb * BTILE;
#pragma unroll
        for (int s = 0; s < 2; s++) {
            const int ks = kw * 2 + s;
            uint32_t ah[2][4], al[2][4];
#pragma unroll
            for (int mt = 0; mt < 2; mt++) {
                uint32_t ao = ab + a_lrow + mt * (16 * LDA) + ks * 32;
                ldsm_x4(ah[mt], ao);
                ldsm_x4(al[mt], ao + ATILE);
            }
            uint32_t zb[NBL][4];
#pragma unroll
            for (int bt = 0; bt < NBL; bt++) {
                int krow = ks * 16 + (lane & 15);
                int ncol = wc * CW + bt * 16 + (lane >> 4) * 8;
                ldsm_x4_t(zb[bt], bb + (uint32_t)(krow * LDB + ncol * 2));
            }
#pragma unroll
            for (int mt = 0; mt < 2; mt++)
#pragma unroll
                for (int nt = 0; nt < NTN; nt++) {
                    const int g = nt >> 1, p = (nt & 1) * 2;
                    mma_f16(acc[mt][nt], ah[mt], zb[g][p], zb[g][p + 1]);
                    mma_f16(acc[mt][nt], al[mt], zb[g][p], zb[g][p + 1]);
                }
        }
    };

    issueB(0); CP_COMMIT();
    issueB(1); CP_COMMIT();
    prefA(0);
    cvtSTS(0);
    prefA(1);

    for (int i = 0; i < NCH; i++) {
        const int sa = i & 1, sb = i % 3;
        CP_WAIT1();
        __syncthreads();
        compute(sa, sb);
        if (i + 2 < NCH) { issueB(i + 2); CP_COMMIT(); }
        if (i + 1 < NCH) {
            cvtSTS((i + 1) & 1);
            if (i + 2 < NCH) prefA(i + 2);
        }
    }

    // merge k-halves
    __syncthreads();
    float* ps = reinterpret_cast<float*>(sm);
    if (kw == 1) {
#pragma unroll
        for (int mt = 0; mt < 2; mt++)
#pragma unroll
            for (int nt = 0; nt < NTN; nt++)
#pragma unroll
                for (int q = 0; q < 4; q++)
                    ps[((((wi * 2 + mt) * NTN + nt) * 4) + q) * 32 + lane] =
                        acc[mt][nt][q];
    }
    __syncthreads();
    if (kw == 0) {
        const int g = lane >> 2, cp2 = (lane & 3) * 2;
#pragma unroll
        for (int mt = 0; mt < 2; mt++) {
            const int r0 = m0 + wr * 32 + mt * 16 + g;
#pragma unroll
            for (int nt = 0; nt < NTN; nt++) {
                const int col = wc * CW + nt * 8 + cp2;
                float p[4];
#pragma unroll
                for (int q = 0; q < 4; q++)
                    p[q] = acc[mt][nt][q] +
                        ps[((((wi * 2 + mt) * NTN + nt) * 4) + q) * 32 + lane];
#pragma unroll
                for (int half = 0; half < 2; half++) {
                    const size_t row = (size_t)(r0 + half * 8);
                    float2 yv = *reinterpret_cast<const float2*>(y + row * BN + col);
                    float v0 = p[2 * half + 0] * A_INV + yv.x;
                    float v1 = p[2 * half + 1] * A_INV + yv.y;
                    if (relu) { v0 = fmaxf(v0, 0.f); v1 = fmaxf(v1, 0.f); }
                    *reinterpret_cast<float2*>(out + row * BN + col) =
                        make_float2(v0, v1);
                }
            }
        }
    }
}

// ── fused projection: y = A@W[0:K] + b ; z = A@W[K:2K] -> fp16 ──
template <int BN>
__global__ __launch_bounds__(256, 2) void proj_k(
    const float* __restrict__ A,
    const float* __restrict__ W,
    const float* __restrict__ bias,
    float* __restrict__ yout,
    __half* __restrict__ zh,
    int K)
{
    constexpr int NT = 256, BM = 32, BK = 32, TM = 2, TN = BN / 16;
    constexpr int BF4 = (BK * BN / 4) / NT;
    __shared__ float As[BK][BM];
    __shared__ float Bs[BK][BN];
    __shared__ float Bn[BK][BN];

    const float* Ws = W;
    const float* Wn = W + (size_t)K * BN;
    const int tid = threadIdx.x;
    const int tx = tid % (BN / TN), ty = tid / (BN / TN);
    const int m0 = blockIdx.x * BM;

    float accS[TM][TN], accN[TM][TN];
#pragma unroll
    for (int i = 0; i < TM; i++)
#pragma unroll
        for (int j = 0; j < TN; j++) { accS[i][j] = 0.f; accN[i][j] = 0.f; }

    float4 ra, rs[BF4], rn[BF4];
    const int nkt = K / BK;

    {
        int row = tid >> 3, k4 = tid & 7;
        ra = *reinterpret_cast<const float4*>(A + (size_t)(m0 + row) * K + k4 * 4);
    }
#pragma unroll
    for (int u = 0; u < BF4; u++) {
        int id = tid + u * NT, row = id / (BN / 4), c4 = id % (BN / 4);
        rs[u] = *reinterpret_cast<const float4*>(Ws + (size_t)row * BN + c4 * 4);
        rn[u] = *reinterpret_cast<const float4*>(Wn + (size_t)row * BN + c4 * 4);
    }

    for (int kt = 0; kt < nkt; ++kt) {
        {
            int row = tid >> 3, k4 = tid & 7;
            As[k4 * 4 + 0][row] = ra.x; As[k4 * 4 + 1][row] = ra.y;
            As[k4 * 4 + 2][row] = ra.z; As[k4 * 4 + 3][row] = ra.w;
        }
#pragma unroll
        for (int u = 0; u < BF4; u++) {
            int id = tid + u * NT, row = id / (BN / 4), c4 = id % (BN / 4);
            *reinterpret_cast<float4*>(&Bs[row][c4 * 4]) = rs[u];
            *reinterpret_cast<float4*>(&Bn[row][c4 * 4]) = rn[u];
        }
        __syncthreads();
        if (kt + 1 < nkt) {
            const int kb = (kt + 1) * BK;
            {
                int row = tid >> 3, k4 = tid & 7;
                ra = *reinterpret_cast<const float4*>(
                    A + (size_t)(m0 + row) * K + kb + k4 * 4);
            }
#pragma unroll
            for (int u = 0; u < BF4; u++) {
                int id = tid + u * NT, row = id / (BN / 4), c4 = id % (BN / 4);
                rs[u] = *reinterpret_cast<const float4*>(
                    Ws + (size_t)(kb + row) * BN + c4 * 4);
                rn[u] = *reinterpret_cast<const float4*>(
                    Wn + (size_t)(kb + row) * BN + c4 * 4);
            }
        }
#pragma unroll
        for (int k = 0; k < BK; k++) {
            float a0 = As[k][ty * TM], a1 = As[k][ty * TM + 1];
            float bs[TN], bn[TN];
#pragma unroll
            for (int j = 0; j < TN; j += 4) {
                *reinterpret_cast<float4*>(bs + j) =
                    *reinterpret_cast<const float4*>(&Bs[k][tx * TN + j]);
                *reinterpret_cast<float4*>(bn + j) =
                    *reinterpret_cast<const float4*>(&Bn[k][tx * TN + j]);
            }
#pragma unroll
            for (int j = 0; j < TN; j++) {
                accS[0][j] = fmaf(a0, bs[j], accS[0][j]);
                accS[1][j] = fmaf(a1, bs[j], accS[1][j]);
                accN[0][j] = fmaf(a0, bn[j], accN[0][j]);
                accN[1][j] = fmaf(a1, bn[j], accN[1][j]);
            }
        }
        __syncthreads();
    }

#pragma unroll
    for (int i = 0; i < TM; i++) {
        const int row = m0 + ty * TM + i;
#pragma unroll
        for (int j = 0; j < TN; j += 4) {
            const int col = tx * TN + j;
            float4 v = make_float4(accS[i][j], accS[i][j+1], accS[i][j+2], accS[i][j+3]);
            float4 c = *reinterpret_cast<const float4*>(bias + col);
            v.x += c.x; v.y += c.y; v.z += c.z; v.w += c.w;
            *reinterpret_cast<float4*>(yout + (size_t)row * BN + col) = v;
        }
#pragma unroll
        for (int j = 0; j < TN; j += 2) {
            const int col = tx * TN + j;
            *reinterpret_cast<uint32_t*>(zh + (size_t)row * BN + col) =
                packh2(accN[i][j], accN[i][j + 1]);
        }
    }
}

extern "C" void kernel_launch(void* const* d_in, const int* in_sizes, int n_in,
                              void* d_out, int out_size)
{
    const float* x   = (const float*)d_in[0];
    const float* adj = (const float*)d_in[1];
    const float* W1  = (const float*)d_in[2];
    const float* b1  = (const float*)d_in[3];
    const float* W2  = (const float*)d_in[4];
    const float* b2  = (const float*)d_in[5];
    const float* W3  = (const float*)d_in[6];
    const float* b3  = (const float*)d_in[7];
    const float* W4  = (const float*)d_in[8];
    const float* b4  = (const float*)d_in[9];
    float* out = (float*)d_out;

    float *y, *h1, *h2;
    __half* zh;
    cudaGetSymbolAddress((void**)&y,  g_y);
    cudaGetSymbolAddress((void**)&h1, g_h1);
    cudaGetSymbolAddress((void**)&h2, g_h2);
    cudaGetSymbolAddress((void**)&zh, g_zh);

    // smem: A 2 stages (hi+lo, LDA=144) + B 3 stages (single fp16)
    constexpr int SM128 = 2 * (2 * 64 * 144) + 3 * (64 * (128 * 2 + 16)); // 89088
    constexpr int SM64  = 2 * (2 * 64 * 144) + 3 * (64 * (64 * 2 + 16));  // 64512
    cudaFuncSetAttribute(agg_k<128>, cudaFuncAttributeMaxDynamicSharedMemorySize, SM128);
    cudaFuncSetAttribute(agg_k<64>,  cudaFuncAttributeMaxDynamicSharedMemorySize, SM64);

    const dim3 pg(MROWS / 32);
    const dim3 ag(MROWS / 64);

    proj_k<128><<<pg, 256>>>(x, W1, b1, y, zh, 256);
    agg_k<128><<<ag, 512, SM128>>>(adj, zh, y, h1, 1);

    proj_k<128><<<pg, 256>>>(h1, W2, b2, y, zh, 128);
    agg_k<128><<<ag, 512, SM128>>>(adj, zh, y, h2, 1);

    proj_k<128><<<pg, 256>>>(h2, W3, b3, y, zh, 128);
    agg_k<128><<<ag, 512, SM128>>>(adj, zh, y, h1, 1);

    proj_k<64><<<pg, 256>>>(h1, W4, b4, y, zh, 128);
    agg_k<64><<<ag, 512, SM64>>>(adj, zh, y, out, 0);
}

// round 10
// speedup vs baseline: 1.5949x; 1.1839x over previous
#include <cuda_runtime.h>
#include <cuda_fp16.h>
#include <stdint.h>

// GraphSAGE 4-layer, dense adj. N=8192, F: 256->128->128->64.
// h = act( h@W_self + adj @ (h@W_neigh) + b ).
// R10: pure 1-term fp16 aggregation. adj scaled by 4096 -> fp16 (rel err
// 2^-11, zero-mean, averaged out over K=8192 row-normalized sums); z fp16.
// adj@z = (Ah@Z)/4096, fp32 accum. Skeleton: 512-thread split-K warps,
// 2-stage A, 3-stage cp.async B ring, compute-first overlap, smem k-merge.

static constexpr int MROWS = 8192;
static constexpr float A_SCALE = 4096.0f;
static constexpr float A_INV   = 1.0f / 4096.0f;

__device__ float g_y [8192 * 128];
__device__ float g_h1[8192 * 128];
__device__ float g_h2[8192 * 128];
__device__ __half g_zh[8192 * 128];

__device__ __forceinline__ uint32_t smem_u32(const void* p) {
    uint32_t a;
    asm("{ .reg .u64 t; cvta.to.shared.u64 t, %1; cvt.u32.u64 %0, t; }"
        : "=r"(a) : "l"(p));
    return a;
}
__device__ __forceinline__ uint32_t packh2(float a, float b) {
    __half2 t = __floats2half2_rn(a, b);
    return *reinterpret_cast<uint32_t*>(&t);
}
__device__ __forceinline__ void ldsm_x4(uint32_t* r, uint32_t addr) {
    asm volatile("ldmatrix.sync.aligned.m8n8.x4.shared.b16 {%0,%1,%2,%3}, [%4];"
                 : "=r"(r[0]), "=r"(r[1]), "=r"(r[2]), "=r"(r[3]) : "r"(addr));
}
__device__ __forceinline__ void ldsm_x4_t(uint32_t* r, uint32_t addr) {
    asm volatile("ldmatrix.sync.aligned.m8n8.x4.trans.shared.b16 {%0,%1,%2,%3}, [%4];"
                 : "=r"(r[0]), "=r"(r[1]), "=r"(r[2]), "=r"(r[3]) : "r"(addr));
}
__device__ __forceinline__ void mma_f16(float* d, const uint32_t* a,
                                        uint32_t b0, uint32_t b1) {
    asm volatile(
        "mma.sync.aligned.m16n8k16.row.col.f32.f16.f16.f32 "
        "{%0,%1,%2,%3}, {%4,%5,%6,%7}, {%8,%9}, {%0,%1,%2,%3};"
        : "+f"(d[0]), "+f"(d[1]), "+f"(d[2]), "+f"(d[3])
        : "r"(a[0]), "r"(a[1]), "r"(a[2]), "r"(a[3]), "r"(b0), "r"(b1));
}
__device__ __forceinline__ void cp16(uint32_t dst, const void* src) {
    asm volatile("cp.async.ca.shared.global [%0], [%1], 16;" :: "r"(dst), "l"(src));
}
#define CP_COMMIT() asm volatile("cp.async.commit_group;" ::: "memory")
#define CP_WAIT1()  asm volatile("cp.async.wait_group 1;" ::: "memory")

// ── aggregation: out = act(adj @ z + y); 512 threads, split-K warps ──
template <int BN>
__global__ __launch_bounds__(512) void agg_k(
    const float* __restrict__ adj,
    const __half* __restrict__ zh,
    const float* __restrict__ y,
    float* __restrict__ out,
    int relu)
{
    constexpr int NT = 512;
    constexpr int BM = 64, BK = 64, NCH = MROWS / BK;
    constexpr int LDA = 144;                         // 64 fp16 (128B) + 16B pad
    constexpr int ATILE = BM * LDA;                  // single hi tile per stage
    constexpr int LDB = BN * 2 + 16;
    constexpr int BTILE = BK * LDB;
    constexpr int BOFF = 2 * ATILE;                  // A: 2 stages
    constexpr int CW = BN / 4;                       // warp col span (32/16)
    constexpr int NTN = CW / 8;                      // 4 / 2
    constexpr int NBL = NTN / 2;                     // 2 / 1
    constexpr int NCP = BK * BN * 2 / 16;            // cp16 ops per chunk
    constexpr int BCP = (NCP + NT - 1) / NT;         // 2 / 1
    constexpr int CPR = BN / 8;

    extern __shared__ __align__(128) char sm[];
    const uint32_t smb = smem_u32(sm);
    const int tid = threadIdx.x, m0 = blockIdx.x * BM;
    const int w = tid >> 5, lane = tid & 31;
    const int kw = w >> 3;                           // k-half
    const int wi = w & 7;
    const int wr = wi >> 2, wc = wi & 3;             // 2 x 4 tiles of 32x32

    float acc[2][NTN][4];
#pragma unroll
    for (int mt = 0; mt < 2; mt++)
#pragma unroll
        for (int nt = 0; nt < NTN; nt++)
#pragma unroll
            for (int q = 0; q < 4; q++) acc[mt][nt][q] = 0.f;

    float4 ra[2];

    auto prefA = [&](int chunk) {
        const size_t kb = (size_t)chunk * BK;
#pragma unroll
        for (int u = 0; u < 2; u++) {
            int id = tid + u * NT, row = id >> 4, c = id & 15;
            ra[u] = *reinterpret_cast<const float4*>(
                adj + (size_t)(m0 + row) * MROWS + kb + c * 4);
        }
    };
    auto cvtSTS = [&](int sa) {
#pragma unroll
        for (int u = 0; u < 2; u++) {
            int id = tid + u * NT, row = id >> 4, c = id & 15;
            uint32_t h01 = packh2(ra[u].x * A_SCALE, ra[u].y * A_SCALE);
            uint32_t h23 = packh2(ra[u].z * A_SCALE, ra[u].w * A_SCALE);
            uint32_t off = (uint32_t)(row * LDA + c * 8);
            *reinterpret_cast<uint2*>(sm + sa * ATILE + off) = make_uint2(h01, h23);
        }
    };
    auto issueB = [&](int chunk) {
        const uint32_t base = smb + BOFF + (chunk % 3) * BTILE;
        const size_t kb = (size_t)chunk * BK;
#pragma unroll
        for (int u = 0; u < BCP; u++) {
            int id = tid + u * NT;
            if (NCP % NT == 0 || id < NCP) {
                int krow = id / CPR, c = id % CPR;
                uint32_t off = (uint32_t)(krow * LDB + c * 16);
                cp16(base + off, zh + (kb + krow) * BN + c * 8);
            }
        }
    };

    const uint32_t a_lrow =
        (uint32_t)(wr * 32 + (lane & 15)) * LDA + (lane >> 4) * 16;

    auto compute = [&](int sa, int sb) {
        const uint32_t ab = smb + sa * ATILE;
        const uint32_t bb = smb + BOFF + sb * BTILE;
#pragma unroll
        for (int s = 0; s < 2; s++) {
            const int ks = kw * 2 + s;
            uint32_t ah[2][4];
#pragma unroll
            for (int mt = 0; mt < 2; mt++)
                ldsm_x4(ah[mt], ab + a_lrow + mt * (16 * LDA) + ks * 32);
            uint32_t zb[NBL][4];
#pragma unroll
            for (int bt = 0; bt < NBL; bt++) {
                int krow = ks * 16 + (lane & 15);
                int ncol = wc * CW + bt * 16 + (lane >> 4) * 8;
                ldsm_x4_t(zb[bt], bb + (uint32_t)(krow * LDB + ncol * 2));
            }
#pragma unroll
            for (int mt = 0; mt < 2; mt++)
#pragma unroll
                for (int nt = 0; nt < NTN; nt++) {
                    const int g = nt >> 1, p = (nt & 1) * 2;
                    mma_f16(acc[mt][nt], ah[mt], zb[g][p], zb[g][p + 1]);
                }
        }
    };

    issueB(0); CP_COMMIT();
    issueB(1); CP_COMMIT();
    prefA(0);
    cvtSTS(0);
    prefA(1);

    for (int i = 0; i < NCH; i++) {
        const int sa = i & 1, sb = i % 3;
        CP_WAIT1();
        __syncthreads();
        compute(sa, sb);
        if (i + 2 < NCH) { issueB(i + 2); CP_COMMIT(); }
        if (i + 1 < NCH) {
            cvtSTS((i + 1) & 1);
            if (i + 2 < NCH) prefA(i + 2);
        }
    }

    // merge k-halves
    __syncthreads();
    float* ps = reinterpret_cast<float*>(sm);
    if (kw == 1) {
#pragma unroll
        for (int mt = 0; mt < 2; mt++)
#pragma unroll
            for (int nt = 0; nt < NTN; nt++)
#pragma unroll
                for (int q = 0; q < 4; q++)
                    ps[((((wi * 2 + mt) * NTN + nt) * 4) + q) * 32 + lane] =
                        acc[mt][nt][q];
    }
    __syncthreads();
    if (kw == 0) {
        const int g = lane >> 2, cp2 = (lane & 3) * 2;
#pragma unroll
        for (int mt = 0; mt < 2; mt++) {
            const int r0 = m0 + wr * 32 + mt * 16 + g;
#pragma unroll
            for (int nt = 0; nt < NTN; nt++) {
                const int col = wc * CW + nt * 8 + cp2;
                float p[4];
#pragma unroll
                for (int q = 0; q < 4; q++)
                    p[q] = acc[mt][nt][q] +
                        ps[((((wi * 2 + mt) * NTN + nt) * 4) + q) * 32 + lane];
#pragma unroll
                for (int half = 0; half < 2; half++) {
                    const size_t row = (size_t)(r0 + half * 8);
                    float2 yv = *reinterpret_cast<const float2*>(y + row * BN + col);
                    float v0 = p[2 * half + 0] * A_INV + yv.x;
                    float v1 = p[2 * half + 1] * A_INV + yv.y;
                    if (relu) { v0 = fmaxf(v0, 0.f); v1 = fmaxf(v1, 0.f); }
                    *reinterpret_cast<float2*>(out + row * BN + col) =
                        make_float2(v0, v1);
                }
            }
        }
    }
}

// ── fused projection: y = A@W[0:K] + b ; z = A@W[K:2K] -> fp16 ──
template <int BN>
__global__ __launch_bounds__(256, 2) void proj_k(
    const float* __restrict__ A,
    const float* __restrict__ W,
    const float* __restrict__ bias,
    float* __restrict__ yout,
    __half* __restrict__ zh,
    int K)
{
    constexpr int NT = 256, BM = 32, BK = 32, TM = 2, TN = BN / 16;
    constexpr int BF4 = (BK * BN / 4) / NT;
    __shared__ float As[BK][BM];
    __shared__ float Bs[BK][BN];
    __shared__ float Bn[BK][BN];

    const float* Ws = W;
    const float* Wn = W + (size_t)K * BN;
    const int tid = threadIdx.x;
    const int tx = tid % (BN / TN), ty = tid / (BN / TN);
    const int m0 = blockIdx.x * BM;

    float accS[TM][TN], accN[TM][TN];
#pragma unroll
    for (int i = 0; i < TM; i++)
#pragma unroll
        for (int j = 0; j < TN; j++) { accS[i][j] = 0.f; accN[i][j] = 0.f; }

    float4 ra, rs[BF4], rn[BF4];
    const int nkt = K / BK;

    {
        int row = tid >> 3, k4 = tid & 7;
        ra = *reinterpret_cast<const float4*>(A + (size_t)(m0 + row) * K + k4 * 4);
    }
#pragma unroll
    for (int u = 0; u < BF4; u++) {
        int id = tid + u * NT, row = id / (BN / 4), c4 = id % (BN / 4);
        rs[u] = *reinterpret_cast<const float4*>(Ws + (size_t)row * BN + c4 * 4);
        rn[u] = *reinterpret_cast<const float4*>(Wn + (size_t)row * BN + c4 * 4);
    }

    for (int kt = 0; kt < nkt; ++kt) {
        {
            int row = tid >> 3, k4 = tid & 7;
            As[k4 * 4 + 0][row] = ra.x; As[k4 * 4 + 1][row] = ra.y;
            As[k4 * 4 + 2][row] = ra.z; As[k4 * 4 + 3][row] = ra.w;
        }
#pragma unroll
        for (int u = 0; u < BF4; u++) {
            int id = tid + u * NT, row = id / (BN / 4), c4 = id % (BN / 4);
            *reinterpret_cast<float4*>(&Bs[row][c4 * 4]) = rs[u];
            *reinterpret_cast<float4*>(&Bn[row][c4 * 4]) = rn[u];
        }
        __syncthreads();
        if (kt + 1 < nkt) {
            const int kb = (kt + 1) * BK;
            {
                int row = tid >> 3, k4 = tid & 7;
                ra = *reinterpret_cast<const float4*>(
                    A + (size_t)(m0 + row) * K + kb + k4 * 4);
            }
#pragma unroll
            for (int u = 0; u < BF4; u++) {
                int id = tid + u * NT, row = id / (BN / 4), c4 = id % (BN / 4);
                rs[u] = *reinterpret_cast<const float4*>(
                    Ws + (size_t)(kb + row) * BN + c4 * 4);
                rn[u] = *reinterpret_cast<const float4*>(
                    Wn + (size_t)(kb + row) * BN + c4 * 4);
            }
        }
#pragma unroll
        for (int k = 0; k < BK; k++) {
            float a0 = As[k][ty * TM], a1 = As[k][ty * TM + 1];
            float bs[TN], bn[TN];
#pragma unroll
            for (int j = 0; j < TN; j += 4) {
                *reinterpret_cast<float4*>(bs + j) =
                    *reinterpret_cast<const float4*>(&Bs[k][tx * TN + j]);
                *reinterpret_cast<float4*>(bn + j) =
                    *reinterpret_cast<const float4*>(&Bn[k][tx * TN + j]);
            }
#pragma unroll
            for (int j = 0; j < TN; j++) {
                accS[0][j] = fmaf(a0, bs[j], accS[0][j]);
                accS[1][j] = fmaf(a1, bs[j], accS[1][j]);
                accN[0][j] = fmaf(a0, bn[j], accN[0][j]);
                accN[1][j] = fmaf(a1, bn[j], accN[1][j]);
            }
        }
        __syncthreads();
    }

#pragma unroll
    for (int i = 0; i < TM; i++) {
        const int row = m0 + ty * TM + i;
#pragma unroll
        for (int j = 0; j < TN; j += 4) {
            const int col = tx * TN + j;
            float4 v = make_float4(accS[i][j], accS[i][j+1], accS[i][j+2], accS[i][j+3]);
            float4 c = *reinterpret_cast<const float4*>(bias + col);
            v.x += c.x; v.y += c.y; v.z += c.z; v.w += c.w;
            *reinterpret_cast<float4*>(yout + (size_t)row * BN + col) = v;
        }
#pragma unroll
        for (int j = 0; j < TN; j += 2) {
            const int col = tx * TN + j;
            *reinterpret_cast<uint32_t*>(zh + (size_t)row * BN + col) =
                packh2(accN[i][j], accN[i][j + 1]);
        }
    }
}

extern "C" void kernel_launch(void* const* d_in, const int* in_sizes, int n_in,
                              void* d_out, int out_size)
{
    const float* x   = (const float*)d_in[0];
    const float* adj = (const float*)d_in[1];
    const float* W1  = (const float*)d_in[2];
    const float* b1  = (const float*)d_in[3];
    const float* W2  = (const float*)d_in[4];
    const float* b2  = (const float*)d_in[5];
    const float* W3  = (const float*)d_in[6];
    const float* b3  = (const float*)d_in[7];
    const float* W4  = (const float*)d_in[8];
    const float* b4  = (const float*)d_in[9];
    float* out = (float*)d_out;

    float *y, *h1, *h2;
    __half* zh;
    cudaGetSymbolAddress((void**)&y,  g_y);
    cudaGetSymbolAddress((void**)&h1, g_h1);
    cudaGetSymbolAddress((void**)&h2, g_h2);
    cudaGetSymbolAddress((void**)&zh, g_zh);

    // smem: A 2 stages (hi only) + B 3 stages
    constexpr int SM128 = 2 * (64 * 144) + 3 * (64 * (128 * 2 + 16)); // 70656
    constexpr int SM64  = 2 * (64 * 144) + 3 * (64 * (64 * 2 + 16));  // 46080
    cudaFuncSetAttribute(agg_k<128>, cudaFuncAttributeMaxDynamicSharedMemorySize, SM128);
    cudaFuncSetAttribute(agg_k<64>,  cudaFuncAttributeMaxDynamicSharedMemorySize, SM64);

    const dim3 pg(MROWS / 32);
    const dim3 ag(MROWS / 64);

    proj_k<128><<<pg, 256>>>(x, W1, b1, y, zh, 256);
    agg_k<128><<<ag, 512, SM128>>>(adj, zh, y, h1, 1);

    proj_k<128><<<pg, 256>>>(h1, W2, b2, y, zh, 128);
    agg_k<128><<<ag, 512, SM128>>>(adj, zh, y, h2, 1);

    proj_k<128><<<pg, 256>>>(h2, W3, b3, y, zh, 128);
    agg_k<128><<<ag, 512, SM128>>>(adj, zh, y, h1, 1);

    proj_k<64><<<pg, 256>>>(h1, W4, b4, y, zh, 128);
    agg_k<64><<<ag, 512, SM64>>>(adj, zh, y, out, 0);
}